// round 9
// baseline (speedup 1.0000x reference)
#include <cuda_runtime.h>
#include <cstdint>

// ============================================================================
// GroupedExperts: out = (silu(x@gate) * (x@up)) @ down, per expert.
// 8 experts x 2048 tokens, DIM=2048, HIDDEN=5632, fp32.
// Plain sm_103 target => mma.sync m16n8k8 tf32 path (no tcgen05/TMA).
// R9: ldmatrix.x4 fragment loads for A AND B (B pre-transposed to K-major in
// the tf32 pre-round pass) -> mainloop issue count drops ~4x.
// ============================================================================

#define NE    8
#define DIMX  2048
#define HID   5632
#define TPE   2048
#define NTOK  (NE * TPE)

// device scratch (no allocation allowed)
__device__ __align__(256) float g_xc[(size_t)NTOK * DIMX];     // tf32 x
__device__ __align__(256) float g_gc[(size_t)NE * HID * DIMX]; // tf32 gate^T [e][n][k]
__device__ __align__(256) float g_uc[(size_t)NE * HID * DIMX]; // tf32 up^T   [e][n][k]
__device__ __align__(256) float g_dc[(size_t)NE * DIMX * HID]; // tf32 down^T [e][n][k]
__device__ __align__(256) float g_h [(size_t)NTOK * HID];      // tf32 h

// ---- helpers ---------------------------------------------------------------
__device__ __forceinline__ uint32_t sptr(const void* p) {
    uint32_t a;
    asm("{ .reg .u64 t; cvta.to.shared.u64 t, %1; cvt.u32.u64 %0, t; }"
        : "=r"(a) : "l"(p));
    return a;
}
__device__ __forceinline__ void cp16(uint32_t s, const void* g) {
    asm volatile("cp.async.cg.shared.global [%0], [%1], 16;"
                 :: "r"(s), "l"(g) : "memory");
}
__device__ __forceinline__ float rna(float f) {
    uint32_t r;
    asm("cvt.rna.tf32.f32 %0, %1;" : "=r"(r) : "f"(f));
    return __uint_as_float(r);
}
__device__ __forceinline__ void ldsm4(uint32_t* r, uint32_t a) {
    asm volatile("ldmatrix.sync.aligned.m8n8.x4.shared.b16 {%0,%1,%2,%3}, [%4];"
                 : "=r"(r[0]), "=r"(r[1]), "=r"(r[2]), "=r"(r[3]) : "r"(a));
}
__device__ __forceinline__ void mma8(float* d, const uint32_t* a,
                                     uint32_t b0, uint32_t b1) {
    asm volatile(
        "mma.sync.aligned.m16n8k8.row.col.f32.tf32.tf32.f32 "
        "{%0,%1,%2,%3}, {%4,%5,%6,%7}, {%8,%9}, {%0,%1,%2,%3};"
        : "+f"(d[0]), "+f"(d[1]), "+f"(d[2]), "+f"(d[3])
        : "r"(a[0]), "r"(a[1]), "r"(a[2]), "r"(a[3]), "r"(b0), "r"(b1));
}

// ---- prologue: tf32 round (linear) -----------------------------------------
__global__ void cvt_tf32(const float4* __restrict__ in, float4* __restrict__ out,
                         size_t n4) {
    size_t i = (size_t)blockIdx.x * blockDim.x + threadIdx.x;
    const size_t stride = (size_t)gridDim.x * blockDim.x;
    for (; i < n4; i += stride) {
        float4 v = in[i];
        v.x = rna(v.x); v.y = rna(v.y); v.z = rna(v.z); v.w = rna(v.w);
        out[i] = v;
    }
}

// ---- prologue: tf32 round + transpose [e][Kd][Nd] -> [e][Nd][Kd] -----------
__global__ void cvt_t(const float* __restrict__ in, float* __restrict__ out,
                      int Kd, int Nd) {
    __shared__ float t[32][33];
    const size_t eoff = (size_t)blockIdx.z * Kd * Nd;
    const int k0 = blockIdx.y << 5, n0 = blockIdx.x << 5;
    const int tx = threadIdx.x, ty = threadIdx.y;
    #pragma unroll
    for (int i2 = 0; i2 < 4; i2++) {
        int i = ty + i2 * 8;
        t[i][tx] = rna(in[eoff + (size_t)(k0 + i) * Nd + n0 + tx]);
    }
    __syncthreads();
    #pragma unroll
    for (int i2 = 0; i2 < 4; i2++) {
        int i = ty + i2 * 8;
        out[eoff + (size_t)(n0 + i) * Kd + k0 + tx] = t[tx][i];
    }
}

// ---- GEMM config -----------------------------------------------------------
// CTA 128(M) x 128(N) x 32(K); 256 thr, warps 4M x 2N, warp tile 32x64.
// All smem tiles are [128 rows][32 floats] at pitch 36 (conflict-free for
// both cp.async stores and ldmatrix row fetches).
#define STAGES 3
#define PITCH  36
#define TILE_F (128 * PITCH)

template<int NB> struct Cfg {
    static const int STAGE_F = (1 + NB) * TILE_F;
    static const int SMEM_SZ = STAGES * STAGE_F * 4;
};

// EPI 0: C = accG.   EPI 1: C = rna( silu(accG) * accU ).
template<int NB, int EPI>
__global__ void __launch_bounds__(256, (NB == 1 ? 2 : 1)) moe_mma(
    const float* __restrict__ A, const float* __restrict__ B0,
    const float* __restrict__ B1, float* __restrict__ C,
    int K, int Nw)
{
    extern __shared__ float sm[];
    const uint32_t smb = sptr(sm);
    const int tid = threadIdx.x, lid = tid & 31, wid = tid >> 5;
    const int wm = (wid & 3) << 5;
    const int wn = (wid >> 2) << 6;
    const int nb = blockIdx.x << 7;
    const int mb = blockIdx.y << 7;
    const int e  = mb / TPE;
    const float* Ab  = A  + (size_t)mb * K;
    const float* B0b = B0 + ((size_t)e * Nw + nb) * K;   // K-major weights
    const float* B1b = (NB == 2) ? (B1 + ((size_t)e * Nw + nb) * K) : B0b;
    const int NK = K >> 5;
    const int STAGE_F = Cfg<NB>::STAGE_F;

    // ldmatrix lane geometry: group g = lid>>3 supplies matrix g's rows.
    const int lg  = lid >> 3, lr8 = lid & 7;
    const int mrow = (lg & 1) * 8 + lr8;   // row-within-16 for the 4 tiles
    const int mcol = (lg >> 1) * 4;        // col quadrant (0 or 4)

    float accG[2][8][4];
    float accU[NB == 2 ? 2 : 1][8][4];
    #pragma unroll
    for (int mi = 0; mi < 2; mi++)
        #pragma unroll
        for (int ni = 0; ni < 8; ni++)
            #pragma unroll
            for (int q = 0; q < 4; q++) {
                accG[mi][ni][q] = 0.f;
                if (NB == 2) accU[mi][ni][q] = 0.f;
            }

    auto load = [&](int kc, int s) {
        const uint32_t sA = smb + (uint32_t)(s * STAGE_F) * 4;
        const int r = tid >> 3, j = tid & 7;            // 128 rows x 8 chunks
        const uint32_t soff = (uint32_t)(r * PITCH + (j << 2)) * 4;
        const size_t goff = (size_t)r * K + (size_t)kc * 32 + (j << 2);
        #pragma unroll
        for (int i = 0; i < 4; i++) {                   // 4 row-batches of 32
            const uint32_t so = soff + (uint32_t)(i * 32 * PITCH) * 4;
            const size_t go = goff + (size_t)(i * 32) * K;
            cp16(sA + so, Ab + go);
            cp16(sA + TILE_F * 4 + so, B0b + go);
            if (NB == 2) cp16(sA + 2 * TILE_F * 4 + so, B1b + go);
        }
    };

    load(0, 0); asm volatile("cp.async.commit_group;" ::: "memory");
    load(1, 1); asm volatile("cp.async.commit_group;" ::: "memory");
    load(2, 2); asm volatile("cp.async.commit_group;" ::: "memory");

    int s = 0;
    #pragma unroll 1
    for (int kc = 0; kc < NK; kc++) {
        asm volatile("cp.async.wait_group 2;" ::: "memory");
        __syncthreads();

        const uint32_t sA  = smb + (uint32_t)(s * STAGE_F) * 4;
        const uint32_t sB0 = sA + TILE_F * 4;
        const uint32_t sB1 = sB0 + TILE_F * 4;
        // per-thread ldmatrix base addresses (k0 added per ks)
        const uint32_t aAd0 = sA  + (uint32_t)((wm + mrow) * PITCH + mcol) * 4;
        const uint32_t aAd1 = aAd0 + (uint32_t)(16 * PITCH) * 4;
        const uint32_t bRow = (uint32_t)((wn + mrow) * PITCH + mcol) * 4;

        #pragma unroll
        for (int ks = 0; ks < 4; ks++) {
            const uint32_t kb = (uint32_t)(ks << 5);   // k0*4 bytes
            uint32_t af[2][4];
            ldsm4(af[0], aAd0 + kb);
            ldsm4(af[1], aAd1 + kb);
            #pragma unroll
            for (int p = 0; p < 4; p++) {
                const uint32_t brow = bRow + (uint32_t)(p * 16 * PITCH) * 4 + kb;
                uint32_t bg[4];
                ldsm4(bg, sB0 + brow);
                mma8(accG[0][2 * p],     af[0], bg[0], bg[2]);
                mma8(accG[0][2 * p + 1], af[0], bg[1], bg[3]);
                mma8(accG[1][2 * p],     af[1], bg[0], bg[2]);
                mma8(accG[1][2 * p + 1], af[1], bg[1], bg[3]);
                if (NB == 2) {
                    uint32_t bu[4];
                    ldsm4(bu, sB1 + brow);
                    mma8(accU[0][2 * p],     af[0], bu[0], bu[2]);
                    mma8(accU[0][2 * p + 1], af[0], bu[1], bu[3]);
                    mma8(accU[1][2 * p],     af[1], bu[0], bu[2]);
                    mma8(accU[1][2 * p + 1], af[1], bu[1], bu[3]);
                }
            }
        }
        __syncthreads();
        if (kc + STAGES < NK) load(kc + STAGES, s);
        asm volatile("cp.async.commit_group;" ::: "memory");  // fixed cadence
        s = (s + 1 == STAGES) ? 0 : s + 1;
    }

    // ---- epilogue ----
    const int l4 = lid >> 2, lm = lid & 3;
    #pragma unroll
    for (int mi = 0; mi < 2; mi++) {
        #pragma unroll
        for (int h2 = 0; h2 < 2; h2++) {
            const int r = mb + wm + (mi << 4) + (h2 << 3) + l4;
            float* Cr = C + (size_t)r * Nw + nb + wn + (lm << 1);
            #pragma unroll
            for (int ni = 0; ni < 8; ni++) {
                float c0 = accG[mi][ni][h2 * 2 + 0];
                float c1 = accG[mi][ni][h2 * 2 + 1];
                if (EPI) {
                    float u0 = accU[mi][ni][h2 * 2 + 0];
                    float u1 = accU[mi][ni][h2 * 2 + 1];
                    c0 = rna(u0 * (c0 / (1.f + __expf(-c0))));
                    c1 = rna(u1 * (c1 / (1.f + __expf(-c1))));
                }
                *(float2*)(Cr + (ni << 3)) = make_float2(c0, c1);
            }
        }
    }
}

// ---- launch ----------------------------------------------------------------
extern "C" void kernel_launch(void* const* d_in, const int* in_sizes, int n_in,
                              void* d_out, int out_size) {
    (void)in_sizes; (void)n_in; (void)out_size;
    const float* x    = (const float*)d_in[0];
    const float* gate = (const float*)d_in[1];
    const float* up   = (const float*)d_in[2];
    const float* down = (const float*)d_in[3];
    float* out = (float*)d_out;

    void *pxc, *pgc, *puc, *pdc, *ph;
    cudaGetSymbolAddress(&pxc, g_xc);
    cudaGetSymbolAddress(&pgc, g_gc);
    cudaGetSymbolAddress(&puc, g_uc);
    cudaGetSymbolAddress(&pdc, g_dc);
    cudaGetSymbolAddress(&ph,  g_h);

    cudaFuncSetAttribute(moe_mma<2, 1>,
                         cudaFuncAttributeMaxDynamicSharedMemorySize, Cfg<2>::SMEM_SZ);
    cudaFuncSetAttribute(moe_mma<1, 0>,
                         cudaFuncAttributeMaxDynamicSharedMemorySize, Cfg<1>::SMEM_SZ);

    // Prologue: tf32-round x; tf32-round + transpose the three weights
    // ([e][K][N] -> [e][N][K], K-major for ldmatrix-friendly smem tiles).
    cvt_tf32<<<8192, 256>>>((const float4*)x, (float4*)pxc,
                            (size_t)NTOK * DIMX / 4);
    dim3 tb(32, 8);
    cvt_t<<<dim3(HID / 32, DIMX / 32, NE), tb>>>(gate, (float*)pgc, DIMX, HID);
    cvt_t<<<dim3(HID / 32, DIMX / 32, NE), tb>>>(up,   (float*)puc, DIMX, HID);
    cvt_t<<<dim3(DIMX / 32, HID / 32, NE), tb>>>(down, (float*)pdc, HID, DIMX);

    // h = silu(x@gate) * (x@up)   (fused, shared A tile)
    moe_mma<2, 1><<<dim3(HID / 128, NTOK / 128), 256, Cfg<2>::SMEM_SZ>>>(
        (const float*)pxc, (const float*)pgc, (const float*)puc,
        (float*)ph, DIMX, HID);
    // out = h @ down
    moe_mma<1, 0><<<dim3(DIMX / 128, NTOK / 128), 256, Cfg<1>::SMEM_SZ>>>(
        (const float*)ph, (const float*)pdc, nullptr, out, HID, DIMX);
}

// round 10
// speedup vs baseline: 1.1087x; 1.1087x over previous
#include <cuda_runtime.h>
#include <cstdint>

// ============================================================================
// GroupedExperts: out = (silu(x@gate) * (x@up)) @ down, per expert.
// 8 experts x 2048 tokens, DIM=2048, HIDDEN=5632, fp32.
// Plain sm_103 target => mma.sync m16n8k8 tf32 (no tcgen05/TMA).
// R10: smem-crossbar-traffic-minimizing warp tiles.
//   fused gate+up: CTA 128x128, 8 warps 2Mx4N (wt 64x32) -> 128KB/chunk.
//   down:          CTA 128x256, 16 warps 4Mx4N (wt 32x64) -> 94B/MMA.
// Scalar LDS fragments (ldmatrix regressed: same crossbar bytes, worse sched).
// ============================================================================

#define NE    8
#define DIMX  2048
#define HID   5632
#define TPE   2048
#define NTOK  (NE * TPE)

// device scratch (no allocation allowed)
__device__ __align__(256) float g_xc[(size_t)NTOK * DIMX];     // tf32 x
__device__ __align__(256) float g_gc[(size_t)NE * DIMX * HID]; // tf32 gate
__device__ __align__(256) float g_uc[(size_t)NE * DIMX * HID]; // tf32 up
__device__ __align__(256) float g_dc[(size_t)NE * HID * DIMX]; // tf32 down
__device__ __align__(256) float g_h [(size_t)NTOK * HID];      // tf32 h

// ---- helpers ---------------------------------------------------------------
__device__ __forceinline__ uint32_t sptr(const void* p) {
    uint32_t a;
    asm("{ .reg .u64 t; cvta.to.shared.u64 t, %1; cvt.u32.u64 %0, t; }"
        : "=r"(a) : "l"(p));
    return a;
}
__device__ __forceinline__ void cp16(uint32_t s, const void* g) {
    asm volatile("cp.async.cg.shared.global [%0], [%1], 16;"
                 :: "r"(s), "l"(g) : "memory");
}
__device__ __forceinline__ float rna(float f) {
    uint32_t r;
    asm("cvt.rna.tf32.f32 %0, %1;" : "=r"(r) : "f"(f));
    return __uint_as_float(r);
}
__device__ __forceinline__ void mma8(float* d, const uint32_t* a,
                                     uint32_t b0, uint32_t b1) {
    asm volatile(
        "mma.sync.aligned.m16n8k8.row.col.f32.tf32.tf32.f32 "
        "{%0,%1,%2,%3}, {%4,%5,%6,%7}, {%8,%9}, {%0,%1,%2,%3};"
        : "+f"(d[0]), "+f"(d[1]), "+f"(d[2]), "+f"(d[3])
        : "r"(a[0]), "r"(a[1]), "r"(a[2]), "r"(a[3]), "r"(b0), "r"(b1));
}

// ---- prologue: tf32 round --------------------------------------------------
__global__ void cvt_tf32(const float4* __restrict__ in, float4* __restrict__ out,
                         size_t n4) {
    size_t i = (size_t)blockIdx.x * blockDim.x + threadIdx.x;
    const size_t stride = (size_t)gridDim.x * blockDim.x;
    for (; i < n4; i += stride) {
        float4 v = in[i];
        v.x = rna(v.x); v.y = rna(v.y); v.z = rna(v.z); v.w = rna(v.w);
        out[i] = v;
    }
}

// ---- shared constants ------------------------------------------------------
#define STAGES  3
#define APITCH  36
#define A_TILE_F (128 * APITCH)            // 4608 floats

// ===================== fused gate+up kernel =================================
// CTA 128M x 128N x 32K, 256 thr, warps 2Mx4N, warp tile 64x32.
#define BPITCH2  136
#define B_TILE2  (32 * BPITCH2)            // 4352 floats
#define STAGE2_F (A_TILE_F + 2 * B_TILE2)  // 13312 floats
#define SMEM2    (STAGES * STAGE2_F * 4)   // 159744 B

__global__ void __launch_bounds__(256, 1) moe_fused(
    const float* __restrict__ A, const float* __restrict__ B0,
    const float* __restrict__ B1, float* __restrict__ C, int K, int Nw)
{
    extern __shared__ float sm[];
    const uint32_t smb = sptr(sm);
    const int tid = threadIdx.x, lid = tid & 31, wid = tid >> 5;
    const int wm = (wid & 1) << 6;              // 0 / 64
    const int wn = ((wid >> 1) & 3) << 5;       // 0/32/64/96
    const int nb = blockIdx.x << 7;
    const int mb = blockIdx.y << 7;
    const int e  = mb / TPE;
    const float* Ab  = A  + (size_t)mb * K;
    const float* B0b = B0 + (size_t)e * K * Nw + nb;
    const float* B1b = B1 + (size_t)e * K * Nw + nb;
    const int NK = K >> 5;

    float accG[4][4][4], accU[4][4][4];
    #pragma unroll
    for (int mi = 0; mi < 4; mi++)
        #pragma unroll
        for (int ni = 0; ni < 4; ni++)
            #pragma unroll
            for (int q = 0; q < 4; q++) { accG[mi][ni][q] = 0.f; accU[mi][ni][q] = 0.f; }

    auto load = [&](int kc, int s) {
        const uint32_t sA  = smb + (uint32_t)(s * STAGE2_F) * 4;
        const uint32_t sB0 = sA + A_TILE_F * 4;
        const uint32_t sB1 = sB0 + B_TILE2 * 4;
        const float* gA  = Ab + kc * 32;
        const float* gB0 = B0b + (size_t)(kc * 32) * Nw;
        const float* gB1 = B1b + (size_t)(kc * 32) * Nw;
        #pragma unroll
        for (int i = 0; i < 4; i++) {           // A: 128 rows x 32 floats
            int idx = tid + (i << 8); int r = idx >> 3, j = idx & 7;
            cp16(sA + (uint32_t)(r * APITCH + (j << 2)) * 4,
                 gA + (size_t)r * K + (j << 2));
        }
        #pragma unroll
        for (int i = 0; i < 4; i++) {           // B: 32 rows x 128 floats
            int idx = tid + (i << 8); int r = idx >> 5, j = idx & 31;
            const uint32_t so = (uint32_t)(r * BPITCH2 + (j << 2)) * 4;
            const size_t go = (size_t)r * Nw + (j << 2);
            cp16(sB0 + so, gB0 + go);
            cp16(sB1 + so, gB1 + go);
        }
    };

    load(0, 0); asm volatile("cp.async.commit_group;" ::: "memory");
    load(1, 1); asm volatile("cp.async.commit_group;" ::: "memory");
    load(2, 2); asm volatile("cp.async.commit_group;" ::: "memory");

    int s = 0;
    const int l4 = lid >> 2, lm = lid & 3;
    #pragma unroll 1
    for (int kc = 0; kc < NK; kc++) {
        asm volatile("cp.async.wait_group 2;" ::: "memory");
        __syncthreads();

        const float* sA  = sm + s * STAGE2_F;
        const float* sB0 = sA + A_TILE_F;
        const float* sB1 = sB0 + B_TILE2;

        #pragma unroll
        for (int ks = 0; ks < 4; ks++) {
            const int k0 = ks << 3;
            uint32_t af[4][4];
            #pragma unroll
            for (int mi = 0; mi < 4; mi++) {
                const int rb = wm + (mi << 4) + l4;
                const int c  = k0 + lm;
                af[mi][0] = __float_as_uint(sA[rb * APITCH + c]);
                af[mi][1] = __float_as_uint(sA[(rb + 8) * APITCH + c]);
                af[mi][2] = __float_as_uint(sA[rb * APITCH + c + 4]);
                af[mi][3] = __float_as_uint(sA[(rb + 8) * APITCH + c + 4]);
            }
            #pragma unroll
            for (int ni = 0; ni < 4; ni++) {
                const int cb = wn + (ni << 3) + l4;
                const int kr = k0 + lm;
                uint32_t b0 = __float_as_uint(sB0[kr * BPITCH2 + cb]);
                uint32_t b1 = __float_as_uint(sB0[(kr + 4) * BPITCH2 + cb]);
                #pragma unroll
                for (int mi = 0; mi < 4; mi++) mma8(accG[mi][ni], af[mi], b0, b1);
                uint32_t u0 = __float_as_uint(sB1[kr * BPITCH2 + cb]);
                uint32_t u1 = __float_as_uint(sB1[(kr + 4) * BPITCH2 + cb]);
                #pragma unroll
                for (int mi = 0; mi < 4; mi++) mma8(accU[mi][ni], af[mi], u0, u1);
            }
        }
        __syncthreads();
        if (kc + STAGES < NK) load(kc + STAGES, s);
        asm volatile("cp.async.commit_group;" ::: "memory");  // fixed cadence
        s = (s + 1 == STAGES) ? 0 : s + 1;
    }

    // epilogue: h = rna( silu(g) * u )
    #pragma unroll
    for (int mi = 0; mi < 4; mi++) {
        #pragma unroll
        for (int h2 = 0; h2 < 2; h2++) {
            const int r = mb + wm + (mi << 4) + (h2 << 3) + l4;
            float* Cr = C + (size_t)r * Nw + nb + wn + (lm << 1);
            #pragma unroll
            for (int ni = 0; ni < 4; ni++) {
                float g0 = accG[mi][ni][h2 * 2 + 0];
                float g1 = accG[mi][ni][h2 * 2 + 1];
                float u0 = accU[mi][ni][h2 * 2 + 0];
                float u1 = accU[mi][ni][h2 * 2 + 1];
                float c0 = rna(u0 * (g0 / (1.f + __expf(-g0))));
                float c1 = rna(u1 * (g1 / (1.f + __expf(-g1))));
                *(float2*)(Cr + (ni << 3)) = make_float2(c0, c1);
            }
        }
    }
}

// ===================== down-proj kernel =====================================
// CTA 128M x 256N x 32K, 512 thr, warps 4Mx4N, warp tile 32x64.
#define BPITCHD  264
#define B_TILED  (32 * BPITCHD)            // 8448 floats
#define STAGED_F (A_TILE_F + B_TILED)      // 13056 floats
#define SMEMD    (STAGES * STAGED_F * 4)   // 156672 B

__global__ void __launch_bounds__(512, 1) moe_down(
    const float* __restrict__ A, const float* __restrict__ B0,
    float* __restrict__ C, int K, int Nw)
{
    extern __shared__ float sm[];
    const uint32_t smb = sptr(sm);
    const int tid = threadIdx.x, lid = tid & 31, wid = tid >> 5;
    const int wm = (wid & 3) << 5;              // 0..96
    const int wn = (wid >> 2) << 6;             // 0..192
    const int nb = blockIdx.x << 8;             // 256-wide N tile
    const int mb = blockIdx.y << 7;
    const int e  = mb / TPE;
    const float* Ab  = A  + (size_t)mb * K;
    const float* B0b = B0 + (size_t)e * K * Nw + nb;
    const int NK = K >> 5;

    float acc[2][8][4];
    #pragma unroll
    for (int mi = 0; mi < 2; mi++)
        #pragma unroll
        for (int ni = 0; ni < 8; ni++)
            #pragma unroll
            for (int q = 0; q < 4; q++) acc[mi][ni][q] = 0.f;

    auto load = [&](int kc, int s) {
        const uint32_t sA = smb + (uint32_t)(s * STAGED_F) * 4;
        const uint32_t sB = sA + A_TILE_F * 4;
        const float* gA = Ab + kc * 32;
        const float* gB = B0b + (size_t)(kc * 32) * Nw;
        #pragma unroll
        for (int i = 0; i < 2; i++) {           // A: 128 rows x 32 floats
            int idx = tid + (i << 9); int r = idx >> 3, j = idx & 7;
            cp16(sA + (uint32_t)(r * APITCH + (j << 2)) * 4,
                 gA + (size_t)r * K + (j << 2));
        }
        #pragma unroll
        for (int i = 0; i < 4; i++) {           // B: 32 rows x 256 floats
            int idx = tid + (i << 9); int r = idx >> 6, j = idx & 63;
            cp16(sB + (uint32_t)(r * BPITCHD + (j << 2)) * 4,
                 gB + (size_t)r * Nw + (j << 2));
        }
    };

    load(0, 0); asm volatile("cp.async.commit_group;" ::: "memory");
    load(1, 1); asm volatile("cp.async.commit_group;" ::: "memory");
    load(2, 2); asm volatile("cp.async.commit_group;" ::: "memory");

    int s = 0;
    const int l4 = lid >> 2, lm = lid & 3;
    #pragma unroll 1
    for (int kc = 0; kc < NK; kc++) {
        asm volatile("cp.async.wait_group 2;" ::: "memory");
        __syncthreads();

        const float* sA = sm + s * STAGED_F;
        const float* sB = sA + A_TILE_F;

        #pragma unroll
        for (int ks = 0; ks < 4; ks++) {
            const int k0 = ks << 3;
            uint32_t af[2][4];
            #pragma unroll
            for (int mi = 0; mi < 2; mi++) {
                const int rb = wm + (mi << 4) + l4;
                const int c  = k0 + lm;
                af[mi][0] = __float_as_uint(sA[rb * APITCH + c]);
                af[mi][1] = __float_as_uint(sA[(rb + 8) * APITCH + c]);
                af[mi][2] = __float_as_uint(sA[rb * APITCH + c + 4]);
                af[mi][3] = __float_as_uint(sA[(rb + 8) * APITCH + c + 4]);
            }
            #pragma unroll
            for (int ni = 0; ni < 8; ni++) {
                const int cb = wn + (ni << 3) + l4;
                const int kr = k0 + lm;
                uint32_t b0 = __float_as_uint(sB[kr * BPITCHD + cb]);
                uint32_t b1 = __float_as_uint(sB[(kr + 4) * BPITCHD + cb]);
                mma8(acc[0][ni], af[0], b0, b1);
                mma8(acc[1][ni], af[1], b0, b1);
            }
        }
        __syncthreads();
        if (kc + STAGES < NK) load(kc + STAGES, s);
        asm volatile("cp.async.commit_group;" ::: "memory");  // fixed cadence
        s = (s + 1 == STAGES) ? 0 : s + 1;
    }

    // epilogue
    #pragma unroll
    for (int mi = 0; mi < 2; mi++) {
        #pragma unroll
        for (int h2 = 0; h2 < 2; h2++) {
            const int r = mb + wm + (mi << 4) + (h2 << 3) + l4;
            float* Cr = C + (size_t)r * Nw + nb + wn + (lm << 1);
            #pragma unroll
            for (int ni = 0; ni < 8; ni++) {
                *(float2*)(Cr + (ni << 3)) =
                    make_float2(acc[mi][ni][h2 * 2 + 0], acc[mi][ni][h2 * 2 + 1]);
            }
        }
    }
}

// ---- launch ----------------------------------------------------------------
extern "C" void kernel_launch(void* const* d_in, const int* in_sizes, int n_in,
                              void* d_out, int out_size) {
    (void)in_sizes; (void)n_in; (void)out_size;
    const float* x    = (const float*)d_in[0];
    const float* gate = (const float*)d_in[1];
    const float* up   = (const float*)d_in[2];
    const float* down = (const float*)d_in[3];
    float* out = (float*)d_out;

    void *pxc, *pgc, *puc, *pdc, *ph;
    cudaGetSymbolAddress(&pxc, g_xc);
    cudaGetSymbolAddress(&pgc, g_gc);
    cudaGetSymbolAddress(&puc, g_uc);
    cudaGetSymbolAddress(&pdc, g_dc);
    cudaGetSymbolAddress(&ph,  g_h);

    cudaFuncSetAttribute(moe_fused, cudaFuncAttributeMaxDynamicSharedMemorySize, SMEM2);
    cudaFuncSetAttribute(moe_down,  cudaFuncAttributeMaxDynamicSharedMemorySize, SMEMD);

    // Prologue: tf32-round all operands (exact feed-through in GEMMs).
    const size_t nx4 = (size_t)NTOK * DIMX / 4;
    const size_t nw4 = (size_t)NE * DIMX * HID / 4;
    cvt_tf32<<<8192, 256>>>((const float4*)x,    (float4*)pxc, nx4);
    cvt_tf32<<<8192, 256>>>((const float4*)gate, (float4*)pgc, nw4);
    cvt_tf32<<<8192, 256>>>((const float4*)up,   (float4*)puc, nw4);
    cvt_tf32<<<8192, 256>>>((const float4*)down, (float4*)pdc, nw4);

    // h = silu(x@gate) * (x@up)
    moe_fused<<<dim3(HID / 128, NTOK / 128), 256, SMEM2>>>(
        (const float*)pxc, (const float*)pgc, (const float*)puc,
        (float*)ph, DIMX, HID);
    // out = h @ down
    moe_down<<<dim3(DIMX / 256, NTOK / 128), 512, SMEMD>>>(
        (const float*)ph, (const float*)pdc, out, HID, DIMX);
}